// round 3
// baseline (speedup 1.0000x reference)
#include <cuda_runtime.h>
#include <cstdint>
#include <cstddef>

// Reverse LSTM: B=128, T=2048, H=512.
// out[b, t, :] = h at scan step t (which consumed x[b, T-1-t]).
//
// Persistent kernel: 128 CTAs = 4 batch-groups (32 rows) x 32 col-groups (16 h-cols
// -> 64 z-cols: i,f,g,o). Wh slice (512x64 f32 = 128KB) lives in SMEM for all steps.
// Per step: stage h (L2, cp.async.cg bypassing L1) -> f32x2-packed register GEMM ->
// gates -> write h to d_out + transposed global double buffer -> per-group barrier.

#define T_STEPS 2048
#define HID     512
#define NBG     4      // batch groups
#define BG_B    32     // batch rows per group
#define CG_J    16     // h-cols per CTA

__device__ float    g_Hbuf[2][NBG][HID * BG_B];  // [parity][bg][k*32 + b]  (k-major!)
__device__ unsigned g_cnt[NBG];

typedef unsigned long long u64;

__device__ __forceinline__ void ffma2(u64 &d, u64 a, u64 b) {
    asm volatile("fma.rn.f32x2 %0, %1, %2, %0;" : "+l"(d) : "l"(a), "l"(b));
}
__device__ __forceinline__ u64 pack2(float x) {
    u64 r; asm("mov.b64 %0, {%1, %1};" : "=l"(r) : "f"(x)); return r;
}
__device__ __forceinline__ void cp16(void* s, const void* g) {
    unsigned sa = (unsigned)__cvta_generic_to_shared(s);
    asm volatile("cp.async.cg.shared.global [%0], [%1], 16;" :: "r"(sa), "l"(g) : "memory");
}

__global__ void lstm_init_kernel() {
    if (threadIdx.x < NBG) g_cnt[threadIdx.x] = 0u;
}

extern __shared__ float sm[];

__global__ void __launch_bounds__(128, 1)
lstm_persistent_kernel(const float* __restrict__ x,
                       const float* __restrict__ Wi,
                       const float* __restrict__ Wh,
                       const float* __restrict__ bias,
                       float* __restrict__ out)
{
    // SMEM layout (floats):
    float* Wh_s = sm;                  // [512][64]   131072 B
    float* h_s  = sm + 32768;          // [512][32]    65536 B  (k-major, batch contiguous)
    float* z_s  = sm + 49152;          // [64][44]     11264 B  (pad 44 -> conflict-free)
    float* x_s  = sm + 51968;          // [32]
    float* wi_s = sm + 52000;          // [64]
    float* b_s  = sm + 52064;          // [64]         total 52128 floats = 208512 B

    const int tid  = threadIdx.x;
    const int bg   = blockIdx.x >> 5;   // 0..3
    const int cg   = blockIdx.x & 31;   // 0..31
    const int lane = tid & 31;          // col-pair index (0..31)
    const int oct  = tid >> 5;          // batch octet (0..3) == warp id

    // ---- One-time: load Wh slice + Wi/bias slice ----
    for (int idx = tid; idx < HID * 64; idx += 128) {
        int k = idx >> 6, c = idx & 63;
        int gcol = (c >> 4) * HID + cg * CG_J + (c & 15);   // gate*512 + cg*16 + j
        Wh_s[idx] = Wh[(size_t)k * (4 * HID) + gcol];
    }
    if (tid < 64) {
        int gcol = (tid >> 4) * HID + cg * CG_J + (tid & 15);
        wi_s[tid] = Wi[gcol];
        b_s[tid]  = bias[gcol];
    }
    __syncthreads();

    // ---- Gate-phase constants (thread owns 4 fixed (b, j) h-outputs) ----
    const int j   = tid & 15;
    const int qu  = tid >> 4;
    const int b0l = qu * 4;
    const float wii = wi_s[j],      wif = wi_s[16 + j];
    const float wig = wi_s[32 + j], wio = wi_s[48 + j];
    const float bii = b_s[j],       bif = b_s[16 + j];
    const float big = b_s[32 + j],  bio = b_s[48 + j];

    float cst[4] = {0.f, 0.f, 0.f, 0.f};

    volatile unsigned* cptr = &g_cnt[bg];
    const size_t TH = (size_t)T_STEPS * HID;

    for (int t = 0; t < T_STEPS; ++t) {
        // ---- Stage h (prev step) from global double buffer, L1-bypassed ----
        if (t > 0) {
            const float* src = &g_Hbuf[t & 1][bg][0];
            #pragma unroll 8
            for (int i = tid; i < (HID * BG_B) / 4; i += 128)
                cp16(h_s + 4 * i, src + 4 * i);
            asm volatile("cp.async.commit_group;" ::: "memory");
        }
        if (tid < BG_B)
            x_s[tid] = x[(size_t)(bg * BG_B + tid) * T_STEPS + (T_STEPS - 1 - t)];
        if (t > 0)
            asm volatile("cp.async.wait_group 0;" ::: "memory");
        __syncthreads();

        // ---- GEMM: z[32][64] = h[32][512] @ Wh_s[512][64], f32x2 packed ----
        u64 a00 = 0, a01 = 0, a02 = 0, a03 = 0;
        u64 a10 = 0, a11 = 0, a12 = 0, a13 = 0;
        if (t > 0) {
            const float* hp = h_s + oct * 8;     // h pairs for this octet, k-major
            const float* wp = Wh_s + lane * 2;   // this thread's 2 cols
            #pragma unroll 8
            for (int k = 0; k < HID; ++k) {
                ulonglong2 hA = *(const ulonglong2*)(hp + k * 32);      // (b0,b1),(b2,b3)
                ulonglong2 hB = *(const ulonglong2*)(hp + k * 32 + 4);  // (b4,b5),(b6,b7)
                float2 w = *(const float2*)(wp + k * 64);
                u64 W0 = pack2(w.x), W1 = pack2(w.y);
                ffma2(a00, hA.x, W0); ffma2(a01, hA.y, W0);
                ffma2(a02, hB.x, W0); ffma2(a03, hB.y, W0);
                ffma2(a10, hA.x, W1); ffma2(a11, hA.y, W1);
                ffma2(a12, hB.x, W1); ffma2(a13, hB.y, W1);
            }
        }

        // ---- Scatter z tile to SMEM (rows = z-col, cols = batch) ----
        {
            float* z0 = z_s + (2 * lane)     * 44 + oct * 8;
            float* z1 = z_s + (2 * lane + 1) * 44 + oct * 8;
            *(u64*)(z0 + 0) = a00; *(u64*)(z0 + 2) = a01;
            *(u64*)(z0 + 4) = a02; *(u64*)(z0 + 6) = a03;
            *(u64*)(z1 + 0) = a10; *(u64*)(z1 + 2) = a11;
            *(u64*)(z1 + 4) = a12; *(u64*)(z1 + 6) = a13;
        }
        __syncthreads();

        // ---- Gates + state update + publish h ----
        {
            float4 zi = *(const float4*)(z_s + j * 44 + b0l);
            float4 zf = *(const float4*)(z_s + (16 + j) * 44 + b0l);
            float4 zg = *(const float4*)(z_s + (32 + j) * 44 + b0l);
            float4 zo = *(const float4*)(z_s + (48 + j) * 44 + b0l);
            float4 xv = *(const float4*)(x_s + b0l);
            float zi_[4] = {zi.x, zi.y, zi.z, zi.w};
            float zf_[4] = {zf.x, zf.y, zf.z, zf.w};
            float zg_[4] = {zg.x, zg.y, zg.z, zg.w};
            float zo_[4] = {zo.x, zo.y, zo.z, zo.w};
            float xv_[4] = {xv.x, xv.y, xv.z, xv.w};
            float hv[4];

            size_t obase = (size_t)(bg * BG_B + b0l) * TH + (size_t)t * HID + cg * CG_J + j;
            #pragma unroll
            for (int r = 0; r < 4; ++r) {
                float xr = xv_[r];
                float vi = zi_[r] + xr * wii + bii;
                float vf = zf_[r] + xr * wif + bif;
                float vg = zg_[r] + xr * wig + big;
                float vo = zo_[r] + xr * wio + bio;
                float ig = 1.0f / (1.0f + __expf(-vi));
                float fg = 1.0f / (1.0f + __expf(-vf));
                float eg = __expf(2.0f * vg);
                float gv = 1.0f - 2.0f / (eg + 1.0f);     // tanh(vg)
                float og = 1.0f / (1.0f + __expf(-vo));
                float cn = fg * cst[r] + ig * gv;
                cst[r] = cn;
                float ec = __expf(2.0f * cn);
                float hr = og * (1.0f - 2.0f / (ec + 1.0f));
                hv[r] = hr;
                out[obase + (size_t)r * TH] = hr;
            }
            // transposed (k-major) publish for next step's GEMM broadcast loads
            float* hn = &g_Hbuf[(t + 1) & 1][bg][(cg * CG_J + j) * BG_B + b0l];
            *(float4*)hn = make_float4(hv[0], hv[1], hv[2], hv[3]);
        }

        // ---- Per-batch-group release/acquire barrier (32 CTAs) ----
        __syncthreads();
        if (tid == 0) {
            __threadfence();
            atomicAdd(&g_cnt[bg], 1u);
            unsigned tgt = (unsigned)(t + 1) * 32u;
            while (*cptr < tgt) { }
        }
        __syncthreads();
    }
}

extern "C" void kernel_launch(void* const* d_in, const int* in_sizes, int n_in,
                              void* d_out, int out_size)
{
    // inputs: [0]=s (unused), [1]=x (128*2048), [2]=Wi (2048), [3]=Wh (512*2048), [4]=b (2048)
    const float* x    = (const float*)d_in[1];
    const float* Wi   = (const float*)d_in[2];
    const float* Wh   = (const float*)d_in[3];
    const float* bias = (const float*)d_in[4];
    float* out = (float*)d_out;

    size_t smem = 52128 * sizeof(float);  // 208512 B
    cudaFuncSetAttribute(lstm_persistent_kernel,
                         cudaFuncAttributeMaxDynamicSharedMemorySize, (int)smem);

    lstm_init_kernel<<<1, 32>>>();
    lstm_persistent_kernel<<<128, 128, smem>>>(x, Wi, Wh, bias, out);
}